// round 4
// baseline (speedup 1.0000x reference)
#include <cuda_runtime.h>

// CompetingRiskTabMLoss: Cox PH partial likelihood (Breslow, K causes) + CE, blended.
// Inputs (metadata order): log_h (N,M,K) f32, logits (N,M,5) f32, durations (N,) f32,
//                          event_type (N,) i32, labels (N,) i32.  Output: scalar f32.

#define KC 4
#define NCLS 5
#define NB 32768            // duration buckets (durations ~ U[0,1))
#define NMAX 1000000
#define SCAN_T 1024
#define PER_T (NB / SCAN_T) // 32
#define EPS 1e-8
#define ALPHA 0.4

// ---- scratch (no allocations allowed) ----
__device__ float  g_eta[(size_t)NMAX * KC];     // clipped ensemble-mean log-hazards
__device__ float  g_sdur[NMAX];                 // bucket-sorted durations
__device__ float  g_sf[(size_t)KC * NMAX];      // bucket-sorted exp(eta), SoA per cause
__device__ int    g_cnt[NB];
__device__ int    g_cursor[NB];
__device__ int    g_start[NB + 1];
__device__ double g_bsum[NB * KC];              // per-bucket sum of exp(eta) per cause
__device__ double g_sufx[NB * KC];              // suffix sums over buckets > b
__device__ double g_evsum[KC];
__device__ double g_evcnt[KC];
__device__ double g_ce;

// ---------------------------------------------------------------- init
__global__ void k_init() {
    int i = blockIdx.x * blockDim.x + threadIdx.x;
    if (i < NB * KC) { g_bsum[i] = 0.0; }
    if (i < NB)      { g_cnt[i] = 0; g_cursor[i] = 0; }
    if (i < KC)      { g_evsum[i] = 0.0; g_evcnt[i] = 0.0; }
    if (i == 0)      { g_ce = 0.0; }
}

__device__ __forceinline__ int bucket_of(float d) {
    int b = (int)(d * (float)NB);
    b = b < 0 ? 0 : (b > NB - 1 ? NB - 1 : b);
    return b;
}

__device__ __forceinline__ double warp_red(double v) {
    #pragma unroll
    for (int o = 16; o; o >>= 1) v += __shfl_down_sync(0xffffffffu, v, o);
    return v;
}

// ---------------------------------------------------------------- pass A
// eta = clip(mean_m log_h), exp(eta) -> bucket sums; CE on mean logits.
__global__ void __launch_bounds__(256) k_passA(const float* __restrict__ log_h,
                        const float* __restrict__ logits,
                        const float* __restrict__ dur,
                        const int*   __restrict__ labels,
                        int n, int M) {
    __shared__ double s_ce;
    if (threadIdx.x == 0) s_ce = 0.0;
    __syncthreads();

    int i = blockIdx.x * blockDim.x + threadIdx.x;
    double ce = 0.0;
    if (i < n) {
        // --- eta / exp(eta) ---
        const float4* lh = reinterpret_cast<const float4*>(log_h) + (size_t)i * M;
        float4 s = make_float4(0.f, 0.f, 0.f, 0.f);
        #pragma unroll 8
        for (int m = 0; m < M; m++) {
            float4 v = lh[m];
            s.x += v.x; s.y += v.y; s.z += v.z; s.w += v.w;
        }
        float inv = 1.0f / (float)M;
        float e0 = fminf(fmaxf(s.x * inv, -50.f), 50.f);
        float e1 = fminf(fmaxf(s.y * inv, -50.f), 50.f);
        float e2 = fminf(fmaxf(s.z * inv, -50.f), 50.f);
        float e3 = fminf(fmaxf(s.w * inv, -50.f), 50.f);
        *reinterpret_cast<float4*>(g_eta + (size_t)i * KC) = make_float4(e0, e1, e2, e3);

        float d = dur[i];
        int b = bucket_of(d);
        atomicAdd(&g_cnt[b], 1);
        atomicAdd(&g_bsum[b * KC + 0], (double)expf(e0));
        atomicAdd(&g_bsum[b * KC + 1], (double)expf(e1));
        atomicAdd(&g_bsum[b * KC + 2], (double)expf(e2));
        atomicAdd(&g_bsum[b * KC + 3], (double)expf(e3));

        // --- CE on mean logits ---
        const float* lg = logits + (size_t)i * M * NCLS;
        float lm[NCLS];
        #pragma unroll
        for (int j = 0; j < NCLS; j++) lm[j] = 0.f;
        int total = M * NCLS;
        if ((total & 3) == 0) {
            const float4* lgv = reinterpret_cast<const float4*>(lg);
            for (int t = 0; t < total / 4; t++) {
                float4 v = lgv[t];
                int base = t * 4;
                lm[(base + 0) % NCLS] += v.x;
                lm[(base + 1) % NCLS] += v.y;
                lm[(base + 2) % NCLS] += v.z;
                lm[(base + 3) % NCLS] += v.w;
            }
        } else {
            for (int t = 0; t < total; t++) lm[t % NCLS] += lg[t];
        }
        float mj[NCLS];
        float mx = -3.4e38f;
        #pragma unroll
        for (int j = 0; j < NCLS; j++) { mj[j] = lm[j] * inv; mx = fmaxf(mx, mj[j]); }
        float se = 0.f;
        #pragma unroll
        for (int j = 0; j < NCLS; j++) se += expf(mj[j] - mx);
        float lse = mx + logf(se);
        int lab = labels[i];
        ce = (double)(lse - mj[lab]);
    }
    // hierarchical reduce of CE
    double v = warp_red(ce);
    if ((threadIdx.x & 31) == 0 && v != 0.0) atomicAdd(&s_ce, v);
    __syncthreads();
    if (threadIdx.x == 0 && s_ce != 0.0) atomicAdd(&g_ce, s_ce);
}

// ---------------------------------------------------------------- scan (1 block)
// exclusive prefix of counts -> starts; per-cause suffix sums of bucket sums.
// No per-thread arrays: g_cnt/g_bsum are L2-resident; re-read on second pass.
__global__ void __launch_bounds__(SCAN_T) k_scan() {
    __shared__ int    sh_i[SCAN_T];
    __shared__ double sh_d[SCAN_T];
    int t = threadIdx.x;

    // phase 1: counts -> exclusive starts
    int run = 0;
    for (int k = 0; k < PER_T; k++) run += g_cnt[t * PER_T + k];
    sh_i[t] = run;
    __syncthreads();
    for (int off = 1; off < SCAN_T; off <<= 1) {
        int v = (t >= off) ? sh_i[t - off] : 0;
        __syncthreads();
        sh_i[t] += v;
        __syncthreads();
    }
    int acc = (t > 0) ? sh_i[t - 1] : 0;
    for (int k = 0; k < PER_T; k++) {
        g_start[t * PER_T + k] = acc;
        acc += g_cnt[t * PER_T + k];
    }
    if (t == SCAN_T - 1) g_start[NB] = sh_i[t];
    __syncthreads();

    // phase 2: suffix sums (sum over buckets strictly greater), per cause
    for (int c = 0; c < KC; c++) {
        double tot = 0.0;
        for (int k = 0; k < PER_T; k++) tot += g_bsum[(t * PER_T + k) * KC + c];
        sh_d[t] = tot;
        __syncthreads();
        for (int off = 1; off < SCAN_T; off <<= 1) {
            double v = (t + off < SCAN_T) ? sh_d[t + off] : 0.0;
            __syncthreads();
            sh_d[t] += v;
            __syncthreads();
        }
        double run2 = sh_d[t] - tot;  // sum over thread-chunks strictly after t
        for (int k = PER_T - 1; k >= 0; k--) {
            g_sufx[(t * PER_T + k) * KC + c] = run2;
            run2 += g_bsum[(t * PER_T + k) * KC + c];
        }
        __syncthreads();
    }
}

// ---------------------------------------------------------------- scatter (counting sort)
__global__ void __launch_bounds__(256) k_scatter(const float* __restrict__ dur, int n) {
    int i = blockIdx.x * blockDim.x + threadIdx.x;
    if (i >= n) return;
    float d = dur[i];
    int b = bucket_of(d);
    int pos = g_start[b] + atomicAdd(&g_cursor[b], 1);
    float4 e = *reinterpret_cast<const float4*>(g_eta + (size_t)i * KC);
    g_sdur[pos] = d;
    g_sf[(size_t)0 * NMAX + pos] = expf(e.x);
    g_sf[(size_t)1 * NMAX + pos] = expf(e.y);
    g_sf[(size_t)2 * NMAX + pos] = expf(e.z);
    g_sf[(size_t)3 * NMAX + pos] = expf(e.w);
}

// ---------------------------------------------------------------- events
// denom_i = suffix over higher buckets + same-bucket partial; term = eta - log(denom+eps)
__global__ void __launch_bounds__(256) k_events(const float* __restrict__ dur,
                         const int*   __restrict__ et, int n) {
    __shared__ double s_sum[KC];
    __shared__ double s_cnt[KC];
    int t = threadIdx.x;
    if (t < KC) { s_sum[t] = 0.0; s_cnt[t] = 0.0; }
    __syncthreads();

    int i = blockIdx.x * blockDim.x + t;
    int c = -1;
    double term = 0.0;
    if (i < n) {
        int e = et[i];
        if (e > 0) {
            c = e - 1;
            float d = dur[i];
            int b = bucket_of(d);
            int s0 = g_start[b], s1 = g_start[b + 1];
            const float* fp = g_sf + (size_t)c * NMAX;
            float acc = 0.f;
            for (int j = s0; j < s1; j++) {
                float dj = g_sdur[j];
                float fv = fp[j];
                acc += (dj >= d) ? fv : 0.f;
            }
            double denom = g_sufx[b * KC + c] + (double)acc;
            term = (double)g_eta[(size_t)i * KC + c] - log(denom + EPS);
        }
    }
    #pragma unroll
    for (int cc = 0; cc < KC; cc++) {
        double v = (c == cc) ? term : 0.0;
        double w = (c == cc) ? 1.0  : 0.0;
        v = warp_red(v);
        w = warp_red(w);
        if ((t & 31) == 0 && (w != 0.0)) {
            atomicAdd(&s_sum[cc], v);
            atomicAdd(&s_cnt[cc], w);
        }
    }
    __syncthreads();
    if (t < KC && s_cnt[t] != 0.0) {
        atomicAdd(&g_evsum[t], s_sum[t]);
        atomicAdd(&g_evcnt[t], s_cnt[t]);
    }
}

// ---------------------------------------------------------------- finalize
__global__ void k_fin(float* __restrict__ out, int n) {
    double ls = 0.0;
    #pragma unroll
    for (int c = 0; c < KC; c++) ls += -g_evsum[c] / (g_evcnt[c] + EPS);
    double lc = g_ce / (double)n;
    out[0] = (float)(ALPHA * ls + (1.0 - ALPHA) * lc);
}

// ---------------------------------------------------------------- launch
extern "C" void kernel_launch(void* const* d_in, const int* in_sizes, int n_in,
                              void* d_out, int out_size) {
    const float* log_h  = (const float*)d_in[0];
    const float* logits = (const float*)d_in[1];
    const float* dur    = (const float*)d_in[2];
    const int*   et     = (const int*)d_in[3];
    const int*   labels = (const int*)d_in[4];
    float* out = (float*)d_out;

    int n = in_sizes[2];
    int M = in_sizes[0] / (n * KC);

    int tpb = 256;
    int nb  = (n + tpb - 1) / tpb;
    int initb = (NB * KC + tpb - 1) / tpb;

    k_init<<<initb, tpb>>>();
    k_passA<<<nb, tpb>>>(log_h, logits, dur, labels, n, M);
    k_scan<<<1, SCAN_T>>>();
    k_scatter<<<nb, tpb>>>(dur, n);
    k_events<<<nb, tpb>>>(dur, et, n);
    k_fin<<<1, 1>>>(out, n);
}

// round 8
// speedup vs baseline: 2.3023x; 2.3023x over previous
#include <cuda_runtime.h>

// CompetingRiskTabMLoss: Cox PH partial likelihood (Breslow, K causes) + CE, blended.
// Inputs: log_h (N,M,K) f32, logits (N,M,5) f32, durations (N,) f32,
//         event_type (N,) i32, labels (N,) i32.  Output: scalar f32.

#define KC 4
#define NCLS 5
#define NB 32768             // duration buckets (durations ~ U[0,1))
#define NMAX 1000000
#define NPART 256            // scan partitions
#define BPP (NB / NPART)     // 128 buckets per partition
#define CAP 128              // max bucket elements staged in shared
#define EPS 1e-8
#define ALPHA 0.4

struct __align__(32) Elem {  // 32B: one sector per scattered write
    float dur, f0, f1, f2, f3;
    float cause_bits;        // int cause as float bits
    float pad0, pad1;
};

// ---- scratch (no allocations allowed) ----
__device__ float  g_eta[(size_t)NMAX * KC];
__device__ Elem   g_selem[NMAX];              // bucket-sorted AoS
__device__ int    g_cnt[NB];
__device__ int    g_cursor[NB];
__device__ int    g_start[NB + 1];
__device__ double g_bsum[NB * KC];            // per-bucket sum exp(eta) per cause
__device__ double g_sufx[NB * KC];            // sum over buckets strictly greater
__device__ int    g_part_cnt[NPART];
__device__ int    g_part_start[NPART];
__device__ double g_part_sum[KC * NPART];
__device__ double g_part_sufx[KC * NPART];
__device__ double g_evsum[KC];
__device__ double g_evcnt[KC];
__device__ double g_ce;

// ---------------------------------------------------------------- helpers
__device__ __forceinline__ int bucket_of(float d) {
    int b = (int)(d * (float)NB);
    return b < 0 ? 0 : (b > NB - 1 ? NB - 1 : b);
}
__device__ __forceinline__ double warp_redd(double v) {
    #pragma unroll
    for (int o = 16; o; o >>= 1) v += __shfl_down_sync(0xffffffffu, v, o);
    return v;
}
__device__ __forceinline__ int warp_redi(int v) {
    #pragma unroll
    for (int o = 16; o; o >>= 1) v += __shfl_down_sync(0xffffffffu, v, o);
    return v;
}

// ---------------------------------------------------------------- init
__global__ void k_init() {
    int i = blockIdx.x * blockDim.x + threadIdx.x;
    if (i < NB * KC) g_bsum[i] = 0.0;
    if (i < NB)      { g_cnt[i] = 0; g_cursor[i] = 0; }
    if (i < KC)      { g_evsum[i] = 0.0; g_evcnt[i] = 0.0; }
    if (i == 0)      g_ce = 0.0;
}

// ---------------------------------------------------------------- pass A
// eta = clip(mean_m log_h); exp(eta) -> bucket sums; CE on mean logits.
__global__ void __launch_bounds__(256) k_passA(const float* __restrict__ log_h,
                        const float* __restrict__ logits,
                        const float* __restrict__ dur,
                        const int*   __restrict__ labels,
                        int n, int M) {
    __shared__ double s_ce;
    if (threadIdx.x == 0) s_ce = 0.0;
    __syncthreads();

    int i = blockIdx.x * blockDim.x + threadIdx.x;
    double ce = 0.0;
    if (i < n) {
        const float4* lh = reinterpret_cast<const float4*>(log_h) + (size_t)i * M;
        float4 s = make_float4(0.f, 0.f, 0.f, 0.f);
        #pragma unroll 8
        for (int m = 0; m < M; m++) {
            float4 v = lh[m];
            s.x += v.x; s.y += v.y; s.z += v.z; s.w += v.w;
        }
        float inv = 1.0f / (float)M;
        float e0 = fminf(fmaxf(s.x * inv, -50.f), 50.f);
        float e1 = fminf(fmaxf(s.y * inv, -50.f), 50.f);
        float e2 = fminf(fmaxf(s.z * inv, -50.f), 50.f);
        float e3 = fminf(fmaxf(s.w * inv, -50.f), 50.f);
        *reinterpret_cast<float4*>(g_eta + (size_t)i * KC) = make_float4(e0, e1, e2, e3);

        int b = bucket_of(dur[i]);
        atomicAdd(&g_cnt[b], 1);
        atomicAdd(&g_bsum[b * KC + 0], (double)expf(e0));
        atomicAdd(&g_bsum[b * KC + 1], (double)expf(e1));
        atomicAdd(&g_bsum[b * KC + 2], (double)expf(e2));
        atomicAdd(&g_bsum[b * KC + 3], (double)expf(e3));

        // CE on mean logits
        const float* lg = logits + (size_t)i * M * NCLS;
        float lm[NCLS];
        #pragma unroll
        for (int j = 0; j < NCLS; j++) lm[j] = 0.f;
        int total = M * NCLS;
        if ((total & 3) == 0) {
            const float4* lgv = reinterpret_cast<const float4*>(lg);
            for (int t = 0; t < total / 4; t++) {
                float4 v = lgv[t];
                int base = t * 4;
                lm[(base + 0) % NCLS] += v.x;
                lm[(base + 1) % NCLS] += v.y;
                lm[(base + 2) % NCLS] += v.z;
                lm[(base + 3) % NCLS] += v.w;
            }
        } else {
            for (int t = 0; t < total; t++) lm[t % NCLS] += lg[t];
        }
        float mj[NCLS], mx = -3.4e38f;
        #pragma unroll
        for (int j = 0; j < NCLS; j++) { mj[j] = lm[j] * inv; mx = fmaxf(mx, mj[j]); }
        float se = 0.f;
        #pragma unroll
        for (int j = 0; j < NCLS; j++) se += expf(mj[j] - mx);
        ce = (double)(mx + logf(se) - mj[labels[i]]);
    }
    double v = warp_redd(ce);
    if ((threadIdx.x & 31) == 0 && v != 0.0) atomicAdd(&s_ce, v);
    __syncthreads();
    if (threadIdx.x == 0 && s_ce != 0.0) atomicAdd(&g_ce, s_ce);
}

// ---------------------------------------------------------------- scan A: per-part totals
__global__ void __launch_bounds__(BPP) k_scanA() {
    __shared__ double sd[BPP];
    __shared__ int    si[BPP];
    int t = threadIdx.x, p = blockIdx.x;
    int b = p * BPP + t;

    si[t] = g_cnt[b];
    __syncthreads();
    for (int off = BPP / 2; off; off >>= 1) {
        if (t < off) si[t] += si[t + off];
        __syncthreads();
    }
    if (t == 0) g_part_cnt[p] = si[0];

    for (int c = 0; c < KC; c++) {
        __syncthreads();
        sd[t] = g_bsum[b * KC + c];
        __syncthreads();
        for (int off = BPP / 2; off; off >>= 1) {
            if (t < off) sd[t] += sd[t + off];
            __syncthreads();
        }
        if (t == 0) g_part_sum[c * NPART + p] = sd[0];
    }
}

// ---------------------------------------------------------------- scan B: 1 block over parts
__global__ void __launch_bounds__(NPART) k_scanB() {
    __shared__ int    si[NPART];
    __shared__ double sd[NPART];
    int t = threadIdx.x;

    int own = g_part_cnt[t];
    si[t] = own;
    __syncthreads();
    for (int off = 1; off < NPART; off <<= 1) {
        int v = (t >= off) ? si[t - off] : 0;
        __syncthreads();
        si[t] += v;
        __syncthreads();
    }
    g_part_start[t] = si[t] - own;               // exclusive prefix
    if (t == NPART - 1) g_start[NB] = si[t];     // total

    for (int c = 0; c < KC; c++) {
        __syncthreads();
        double ow = g_part_sum[c * NPART + t];
        sd[t] = ow;
        __syncthreads();
        for (int off = 1; off < NPART; off <<= 1) {
            double v = (t + off < NPART) ? sd[t + off] : 0.0;
            __syncthreads();
            sd[t] += v;
            __syncthreads();
        }
        g_part_sufx[c * NPART + t] = sd[t] - ow; // exclusive suffix
    }
}

// ---------------------------------------------------------------- scan C: within-part fixup
__global__ void __launch_bounds__(BPP) k_scanC() {
    __shared__ int    si[BPP];
    __shared__ double sd[BPP];
    int t = threadIdx.x, p = blockIdx.x;
    int b = p * BPP + t;

    int own = g_cnt[b];
    si[t] = own;
    __syncthreads();
    for (int off = 1; off < BPP; off <<= 1) {
        int v = (t >= off) ? si[t - off] : 0;
        __syncthreads();
        si[t] += v;
        __syncthreads();
    }
    g_start[b] = g_part_start[p] + si[t] - own;

    for (int c = 0; c < KC; c++) {
        __syncthreads();
        double ow = g_bsum[b * KC + c];
        sd[t] = ow;
        __syncthreads();
        for (int off = 1; off < BPP; off <<= 1) {
            double v = (t + off < BPP) ? sd[t + off] : 0.0;
            __syncthreads();
            sd[t] += v;
            __syncthreads();
        }
        g_sufx[b * KC + c] = g_part_sufx[c * NPART + p] + sd[t] - ow;
    }
}

// ---------------------------------------------------------------- scatter (counting sort, AoS 32B)
__global__ void __launch_bounds__(256) k_scatter(const float* __restrict__ dur,
                                                 const int* __restrict__ et, int n) {
    int i = blockIdx.x * blockDim.x + threadIdx.x;
    if (i >= n) return;
    float d = dur[i];
    int b = bucket_of(d);
    int pos = g_start[b] + atomicAdd(&g_cursor[b], 1);
    float4 e = *reinterpret_cast<const float4*>(g_eta + (size_t)i * KC);
    float4* p = reinterpret_cast<float4*>(&g_selem[pos]);
    p[0] = make_float4(d, expf(e.x), expf(e.y), expf(e.z));
    p[1] = make_float4(expf(e.w), __int_as_float(et[i]), 0.f, 0.f);
}

// ---------------------------------------------------------------- events: warp-per-bucket
__global__ void __launch_bounds__(256) k_events() {
    __shared__ float sh_dur[8][CAP];
    __shared__ float sh_f[8][KC][CAP];
    __shared__ int   sh_c[8][CAP];
    __shared__ double s_sum[KC];
    __shared__ double s_cnt[KC];

    int t = threadIdx.x;
    int w = t >> 5, lane = t & 31;
    if (t < KC) { s_sum[t] = 0.0; s_cnt[t] = 0.0; }
    __syncthreads();

    int gwarp = blockIdx.x * 8 + w;
    int nwarps = gridDim.x * 8;

    double acc_sum[KC] = {0.0, 0.0, 0.0, 0.0};
    int    acc_cnt[KC] = {0, 0, 0, 0};

    for (int b = gwarp; b < NB; b += nwarps) {
        int s0 = g_start[b];
        int cnt = g_start[b + 1] - s0;
        if (cnt == 0) continue;
        int m = cnt < CAP ? cnt : CAP;

        // coalesced stage into shared
        for (int j = lane; j < m; j += 32) {
            const float4* p = reinterpret_cast<const float4*>(&g_selem[s0 + j]);
            float4 a = p[0], q = p[1];
            sh_dur[w][j]  = a.x;
            sh_f[w][0][j] = a.y;
            sh_f[w][1][j] = a.z;
            sh_f[w][2][j] = a.w;
            sh_f[w][3][j] = q.x;
            sh_c[w][j]    = __float_as_int(q.y);
        }
        __syncwarp();

        for (int base = 0; base < cnt; base += 32) {
            int j = base + lane;
            int cc = -1;
            float d_e = 0.f, fown = 0.f;
            if (j < cnt) {
                if (j < CAP) {
                    int cv = sh_c[w][j];
                    if (cv > 0) { cc = cv - 1; d_e = sh_dur[w][j]; fown = sh_f[w][cc][j]; }
                } else {  // rare overflow: own element from global
                    const float4* p = reinterpret_cast<const float4*>(&g_selem[s0 + j]);
                    float4 a = p[0], q = p[1];
                    int cv = __float_as_int(q.y);
                    if (cv > 0) {
                        cc = cv - 1; d_e = a.x;
                        fown = (cc == 0) ? a.y : (cc == 1) ? a.z : (cc == 2) ? a.w : q.x;
                    }
                }
            }
            if (cc >= 0) {
                float acc = 0.f;
                const float* fp = sh_f[w][cc];
                for (int j2 = 0; j2 < m; j2++) {
                    float dj = sh_dur[w][j2];
                    acc += (dj >= d_e) ? fp[j2] : 0.f;
                }
                for (int j2 = CAP; j2 < cnt; j2++) {  // rare overflow tail
                    const float4* p = reinterpret_cast<const float4*>(&g_selem[s0 + j2]);
                    float4 a = p[0], q = p[1];
                    float fv = (cc == 0) ? a.y : (cc == 1) ? a.z : (cc == 2) ? a.w : q.x;
                    acc += (a.x >= d_e) ? fv : 0.f;
                }
                double denom = g_sufx[b * KC + cc] + (double)acc;
                acc_sum[cc] += (double)logf(fown) - log(denom + EPS);
                acc_cnt[cc] += 1;
            }
        }
        __syncwarp();
    }

    // reduce: warp -> shared -> global
    #pragma unroll
    for (int c = 0; c < KC; c++) {
        double v = warp_redd(acc_sum[c]);
        int    k = warp_redi(acc_cnt[c]);
        if (lane == 0 && k != 0) {
            atomicAdd(&s_sum[c], v);
            atomicAdd(&s_cnt[c], (double)k);
        }
    }
    __syncthreads();
    if (t < KC && s_cnt[t] != 0.0) {
        atomicAdd(&g_evsum[t], s_sum[t]);
        atomicAdd(&g_evcnt[t], s_cnt[t]);
    }
}

// ---------------------------------------------------------------- finalize
__global__ void k_fin(float* __restrict__ out, int n) {
    double ls = 0.0;
    #pragma unroll
    for (int c = 0; c < KC; c++) ls += -g_evsum[c] / (g_evcnt[c] + EPS);
    double lc = g_ce / (double)n;
    out[0] = (float)(ALPHA * ls + (1.0 - ALPHA) * lc);
}

// ---------------------------------------------------------------- launch
extern "C" void kernel_launch(void* const* d_in, const int* in_sizes, int n_in,
                              void* d_out, int out_size) {
    const float* log_h  = (const float*)d_in[0];
    const float* logits = (const float*)d_in[1];
    const float* dur    = (const float*)d_in[2];
    const int*   et     = (const int*)d_in[3];
    const int*   labels = (const int*)d_in[4];
    float* out = (float*)d_out;

    int n = in_sizes[2];
    int M = in_sizes[0] / (n * KC);

    int tpb = 256;
    int nb  = (n + tpb - 1) / tpb;
    int initb = (NB * KC + tpb - 1) / tpb;

    k_init<<<initb, tpb>>>();
    k_passA<<<nb, tpb>>>(log_h, logits, dur, labels, n, M);
    k_scanA<<<NPART, BPP>>>();
    k_scanB<<<1, NPART>>>();
    k_scanC<<<NPART, BPP>>>();
    k_scatter<<<nb, tpb>>>(dur, et, n);
    k_events<<<512, 256>>>();
    k_fin<<<1, 1>>>(out, n);
}